// round 2
// baseline (speedup 1.0000x reference)
#include <cuda_runtime.h>
#include <stdint.h>

#define DIM 512
#define NN 25000
#define NE 400000
#define BN_EPS 1e-5f

// Scratch (no allocations allowed -> __device__ globals)
__device__ float g_aggr[(size_t)NN * DIM];   // x + segment_sum(msg)
__device__ float g_h1[(size_t)NN * DIM];     // relu(h @ W1 + b1)
__device__ float g_h2[(size_t)NN * DIM];     // h1 @ W2 + b2
__device__ float g_sum[DIM];
__device__ float g_sumsq[DIM];
__device__ float g_mean[DIM];
__device__ float g_istd[DIM];

// ---------------------------------------------------------------------------
// Tiled SGEMM: C[M x 512] = A[M x 512] @ B[512 x 512], 128x128 block, 8x8/thread
// MODE 0: edge conv epilogue: v = relu(acc + bias + x[src][col]); atomicAdd(g_aggr[dst][col], v)
// MODE 1: Cout = relu(acc + bias)
// MODE 2: Cout = acc + bias; accumulate per-column sum & sumsq into g_sum/g_sumsq
// ---------------------------------------------------------------------------
template <int MODE>
__global__ __launch_bounds__(256)
void gemm_kernel(const float* __restrict__ A,
                 const float* __restrict__ B,
                 const float* __restrict__ bias,
                 int M,
                 const float* __restrict__ x,
                 const int* __restrict__ ei,
                 float* __restrict__ Cout,
                 float* __restrict__ aggr)
{
    __shared__ float As[8][128];
    __shared__ float Bs[8][128];

    const int tid = threadIdx.x;
    const int tx = tid & 15;          // 0..15 -> col group
    const int ty = tid >> 4;          // 0..15 -> row group
    const int row0 = blockIdx.y * 128;
    const int col0 = blockIdx.x * 128;

    // A-tile load mapping: 128 rows x 8 k, float4 per thread x1 (2 threads/row)
    const int ar = tid >> 1;          // 0..127
    const int ak = (tid & 1) * 4;     // 0 or 4
    // B-tile load mapping: 8 k x 128 cols, float4 per thread
    const int bk = tid >> 5;          // 0..7
    const int bc = (tid & 31) * 4;    // 0..124

    float acc[8][8];
#pragma unroll
    for (int i = 0; i < 8; i++)
#pragma unroll
        for (int j = 0; j < 8; j++) acc[i][j] = 0.f;

    const int arow = row0 + ar;
    const bool a_ok = (arow < M);
    const float* Aptr = A + (size_t)arow * DIM + ak;

    for (int k0 = 0; k0 < DIM; k0 += 8) {
        float4 av = make_float4(0.f, 0.f, 0.f, 0.f);
        if (a_ok) av = *reinterpret_cast<const float4*>(Aptr + k0);
        As[ak + 0][ar] = av.x;
        As[ak + 1][ar] = av.y;
        As[ak + 2][ar] = av.z;
        As[ak + 3][ar] = av.w;

        float4 bv = *reinterpret_cast<const float4*>(B + (size_t)(k0 + bk) * DIM + col0 + bc);
        *reinterpret_cast<float4*>(&Bs[bk][bc]) = bv;

        __syncthreads();

#pragma unroll
        for (int kk = 0; kk < 8; kk++) {
            float a[8], b[8];
            *reinterpret_cast<float4*>(&a[0]) = *reinterpret_cast<const float4*>(&As[kk][ty * 8]);
            *reinterpret_cast<float4*>(&a[4]) = *reinterpret_cast<const float4*>(&As[kk][ty * 8 + 4]);
            *reinterpret_cast<float4*>(&b[0]) = *reinterpret_cast<const float4*>(&Bs[kk][tx * 8]);
            *reinterpret_cast<float4*>(&b[4]) = *reinterpret_cast<const float4*>(&Bs[kk][tx * 8 + 4]);
#pragma unroll
            for (int i = 0; i < 8; i++)
#pragma unroll
                for (int j = 0; j < 8; j++)
                    acc[i][j] = fmaf(a[i], b[j], acc[i][j]);
        }
        __syncthreads();
    }

    // bias for my 8 columns
    float bb[8];
#pragma unroll
    for (int j = 0; j < 8; j++) bb[j] = bias[col0 + tx * 8 + j];

    if (MODE == 0) {
        // edge epilogue: all rows valid (NE % 128 == 0)
#pragma unroll
        for (int i = 0; i < 8; i++) {
            const int e = row0 + ty * 8 + i;
            const int src = ei[e];
            const int dst = ei[NE + e];
            const float* xr = x + (size_t)src * DIM + col0 + tx * 8;
            float* arp = aggr + (size_t)dst * DIM + col0 + tx * 8;
#pragma unroll
            for (int j = 0; j < 8; j++) {
                float v = acc[i][j] + bb[j] + xr[j];
                v = fmaxf(v, 0.f);
                atomicAdd(arp + j, v);
            }
        }
    } else if (MODE == 1) {
#pragma unroll
        for (int i = 0; i < 8; i++) {
            const int row = row0 + ty * 8 + i;
            if (row < M) {
                float4 o0, o1;
                o0.x = fmaxf(acc[i][0] + bb[0], 0.f);
                o0.y = fmaxf(acc[i][1] + bb[1], 0.f);
                o0.z = fmaxf(acc[i][2] + bb[2], 0.f);
                o0.w = fmaxf(acc[i][3] + bb[3], 0.f);
                o1.x = fmaxf(acc[i][4] + bb[4], 0.f);
                o1.y = fmaxf(acc[i][5] + bb[5], 0.f);
                o1.z = fmaxf(acc[i][6] + bb[6], 0.f);
                o1.w = fmaxf(acc[i][7] + bb[7], 0.f);
                float* cp = Cout + (size_t)row * DIM + col0 + tx * 8;
                *reinterpret_cast<float4*>(cp) = o0;
                *reinterpret_cast<float4*>(cp + 4) = o1;
            }
        }
    } else {
        // MODE 2: store + per-column sum/sumsq
        float cs[8], cq[8];
#pragma unroll
        for (int j = 0; j < 8; j++) { cs[j] = 0.f; cq[j] = 0.f; }
#pragma unroll
        for (int i = 0; i < 8; i++) {
            const int row = row0 + ty * 8 + i;
            if (row < M) {
                float v[8];
#pragma unroll
                for (int j = 0; j < 8; j++) {
                    v[j] = acc[i][j] + bb[j];
                    cs[j] += v[j];
                    cq[j] = fmaf(v[j], v[j], cq[j]);
                }
                float* cp = Cout + (size_t)row * DIM + col0 + tx * 8;
                float4 o0 = make_float4(v[0], v[1], v[2], v[3]);
                float4 o1 = make_float4(v[4], v[5], v[6], v[7]);
                *reinterpret_cast<float4*>(cp) = o0;
                *reinterpret_cast<float4*>(cp + 4) = o1;
            }
        }
        __shared__ float red[16][128];
        __syncthreads();
#pragma unroll
        for (int j = 0; j < 8; j++) red[ty][tx * 8 + j] = cs[j];
        __syncthreads();
        if (tid < 128) {
            float s = 0.f;
#pragma unroll
            for (int t = 0; t < 16; t++) s += red[t][tid];
            atomicAdd(&g_sum[col0 + tid], s);
        }
        __syncthreads();
#pragma unroll
        for (int j = 0; j < 8; j++) red[ty][tx * 8 + j] = cq[j];
        __syncthreads();
        if (tid < 128) {
            float s = 0.f;
#pragma unroll
            for (int t = 0; t < 16; t++) s += red[t][tid];
            atomicAdd(&g_sumsq[col0 + tid], s);
        }
    }
}

__global__ void bn_finalize_kernel()
{
    int c = blockIdx.x * blockDim.x + threadIdx.x;
    if (c < DIM) {
        float mean = g_sum[c] * (1.f / NN);
        float var = g_sumsq[c] * (1.f / NN) - mean * mean;
        g_mean[c] = mean;
        g_istd[c] = rsqrtf(var + BN_EPS);
    }
}

__global__ __launch_bounds__(256)
void bn_apply_kernel(const float* __restrict__ gamma,
                     const float* __restrict__ beta,
                     float* __restrict__ out)
{
    int idx = blockIdx.x * blockDim.x + threadIdx.x;   // float4 index
    if (idx >= NN * DIM / 4) return;
    const int col4 = idx & (DIM / 4 - 1);
    const int c = col4 * 4;
    float4 h = reinterpret_cast<const float4*>(g_h2)[idx];
    float4 m = *reinterpret_cast<const float4*>(&g_mean[c]);
    float4 is = *reinterpret_cast<const float4*>(&g_istd[c]);
    float4 ga = *reinterpret_cast<const float4*>(&gamma[c]);
    float4 be = *reinterpret_cast<const float4*>(&beta[c]);
    float4 o;
    o.x = (h.x - m.x) * is.x * ga.x + be.x;
    o.y = (h.y - m.y) * is.y * ga.y + be.y;
    o.z = (h.z - m.z) * is.z * ga.z + be.z;
    o.w = (h.w - m.w) * is.w * ga.w + be.w;
    reinterpret_cast<float4*>(out)[idx] = o;
}

extern "C" void kernel_launch(void* const* d_in, const int* in_sizes, int n_in,
                              void* d_out, int out_size)
{
    const float* x     = (const float*)d_in[0];
    const int*   ei    = (const int*)d_in[1];     // JAX default x64-disabled -> int32
    const float* eattr = (const float*)d_in[2];
    const float* We    = (const float*)d_in[3];
    const float* be    = (const float*)d_in[4];
    const float* W1    = (const float*)d_in[5];
    const float* b1    = (const float*)d_in[6];
    const float* W2    = (const float*)d_in[7];
    const float* b2    = (const float*)d_in[8];
    const float* gamma = (const float*)d_in[9];
    const float* beta  = (const float*)d_in[10];
    float* out = (float*)d_out;

    void *aggr_p, *h1_p, *h2_p, *sum_p, *sq_p;
    cudaGetSymbolAddress(&aggr_p, g_aggr);
    cudaGetSymbolAddress(&h1_p, g_h1);
    cudaGetSymbolAddress(&h2_p, g_h2);
    cudaGetSymbolAddress(&sum_p, g_sum);
    cudaGetSymbolAddress(&sq_p, g_sumsq);

    // aggr = x  (GIN eps = 0 -> h = x + sum(msg))
    cudaMemcpyAsync(aggr_p, x, sizeof(float) * (size_t)NN * DIM, cudaMemcpyDeviceToDevice);
    cudaMemsetAsync(sum_p, 0, DIM * sizeof(float));
    cudaMemsetAsync(sq_p, 0, DIM * sizeof(float));

    dim3 thr(256);
    // Edge GEMM + gather + relu + scatter-add    (NE % 128 == 0)
    gemm_kernel<0><<<dim3(DIM / 128, NE / 128), thr>>>(
        eattr, We, be, NE, x, ei, nullptr, (float*)aggr_p);

    const int nrb = (NN + 127) / 128;
    // h1 = relu(aggr @ W1 + b1)
    gemm_kernel<1><<<dim3(DIM / 128, nrb), thr>>>(
        (const float*)aggr_p, W1, b1, NN, nullptr, nullptr, (float*)h1_p, nullptr);
    // h2 = h1 @ W2 + b2   (+ column sums for BN)
    gemm_kernel<2><<<dim3(DIM / 128, nrb), thr>>>(
        (const float*)h1_p, W2, b2, NN, nullptr, nullptr, (float*)h2_p, nullptr);

    bn_finalize_kernel<<<2, 256>>>();

    const int n4 = NN * DIM / 4;
    bn_apply_kernel<<<(n4 + 255) / 256, 256>>>(gamma, beta, out);
}

// round 5
// speedup vs baseline: 3.5964x; 3.5964x over previous
#include <cuda_runtime.h>
#include <cuda_bf16.h>
#include <stdint.h>

#define DIM 512
#define NN 25000
#define NE 400000
#define BN_EPS 1e-5f

// ---------------- scratch (device globals; no runtime alloc) ----------------
__device__ __nv_bfloat16 g_eah[(size_t)NE * DIM];
__device__ __nv_bfloat16 g_eal[(size_t)NE * DIM];
__device__ float g_aggr[(size_t)NN * DIM];
__device__ __nv_bfloat16 g_agh[(size_t)NN * DIM];
__device__ __nv_bfloat16 g_agl[(size_t)NN * DIM];
__device__ __nv_bfloat16 g_h1h[(size_t)NN * DIM];
__device__ __nv_bfloat16 g_h1l[(size_t)NN * DIM];
__device__ float g_h2[(size_t)NN * DIM];
__device__ __nv_bfloat16 g_weTh[DIM * DIM], g_weTl[DIM * DIM];
__device__ __nv_bfloat16 g_w1Th[DIM * DIM], g_w1Tl[DIM * DIM];
__device__ __nv_bfloat16 g_w2Th[DIM * DIM], g_w2Tl[DIM * DIM];
__device__ float g_sum[DIM], g_sumsq[DIM], g_mean[DIM], g_istd[DIM];

// ---------------- helpers ----------------
__device__ __forceinline__ uint32_t smem_u32(const void* p) {
    uint32_t a;
    asm("{ .reg .u64 t; cvta.to.shared.u64 t, %1; cvt.u32.u64 %0, t; }" : "=r"(a) : "l"(p));
    return a;
}
#define SW128(off) ((off) ^ (((off) >> 3) & 0x70))

__device__ __forceinline__ void cp16(uint32_t s, const void* g) {
    asm volatile("cp.async.cg.shared.global [%0], [%1], 16;" :: "r"(s), "l"(g));
}
__device__ __forceinline__ void ldm4(uint32_t* r, uint32_t a) {
    asm volatile("ldmatrix.sync.aligned.m8n8.x4.shared.b16 {%0,%1,%2,%3}, [%4];"
        : "=r"(r[0]), "=r"(r[1]), "=r"(r[2]), "=r"(r[3]) : "r"(a));
}
__device__ __forceinline__ void mma16816(float* d, const uint32_t* a, const uint32_t* b) {
    asm volatile("mma.sync.aligned.m16n8k16.row.col.f32.bf16.bf16.f32 "
        "{%0,%1,%2,%3}, {%4,%5,%6,%7}, {%8,%9}, {%0,%1,%2,%3};"
        : "+f"(d[0]), "+f"(d[1]), "+f"(d[2]), "+f"(d[3])
        : "r"(a[0]), "r"(a[1]), "r"(a[2]), "r"(a[3]), "r"(b[0]), "r"(b[1]));
}

// ---------------- prep kernels ----------------
__global__ __launch_bounds__(256) void split_kernel(const float* __restrict__ src,
                                                    __nv_bfloat16* __restrict__ dh,
                                                    __nv_bfloat16* __restrict__ dl,
                                                    size_t n)
{
    size_t i = (size_t)blockIdx.x * blockDim.x + threadIdx.x;
    if (i < n) {
        float v = src[i];
        __nv_bfloat16 h = __float2bfloat16(v);
        dh[i] = h;
        dl[i] = __float2bfloat16(v - __bfloat162float(h));
    }
}

__global__ __launch_bounds__(256) void transpose_split_kernel(const float* __restrict__ W,
                                                              __nv_bfloat16* __restrict__ dh,
                                                              __nv_bfloat16* __restrict__ dl)
{
    int i = blockIdx.x * blockDim.x + threadIdx.x;   // i = n*512 + k
    if (i < DIM * DIM) {
        int n = i >> 9, k = i & 511;
        float v = W[k * DIM + n];
        __nv_bfloat16 h = __float2bfloat16(v);
        dh[i] = h;
        dl[i] = __float2bfloat16(v - __bfloat162float(h));
    }
}

// ---------------- bf16x3 HMMA GEMM ----------------
// C[M x 512] = A[M x 512] @ B[512 x 512] in split precision:
//   acc = Ah*Bh + Al*Bh + Ah*Bl   (24 K-chunks of 64: seg 0,1,2)
// Tile 128x128, 256 thr, 8 warps (4m x 2n), warp tile 32x64.
// MODE 0: edge: v = relu(acc + bias + x[src]); atomicAdd(aggr[dst], v)
// MODE 1: v = relu(acc + bias) -> bf16 hi/lo
// MODE 2: v = acc + bias -> fp32 store
template <int MODE>
__global__ __launch_bounds__(256, 2)
void mma_gemm_kernel(const __nv_bfloat16* __restrict__ Ah,
                     const __nv_bfloat16* __restrict__ Al,
                     const __nv_bfloat16* __restrict__ Bh,   // transposed [N][K]
                     const __nv_bfloat16* __restrict__ Bl,
                     const float* __restrict__ bias,
                     int M,
                     const float* __restrict__ x,
                     const int* __restrict__ ei,
                     float* __restrict__ outf,
                     __nv_bfloat16* __restrict__ outh,
                     __nv_bfloat16* __restrict__ outl)
{
    extern __shared__ char smem[];                    // 2 x (A 16K + B 16K)
    const uint32_t sbase = smem_u32(smem);
    const int tid = threadIdx.x;
    const int wid = tid >> 5, lane = tid & 31;
    const int wm = wid & 3, wn = wid >> 2;
    const int row0 = blockIdx.y * 128;
    const int col0 = blockIdx.x * 128;

    float acc[2][8][4];
#pragma unroll
    for (int i = 0; i < 2; i++)
#pragma unroll
        for (int j = 0; j < 8; j++)
#pragma unroll
            for (int k = 0; k < 4; k++) acc[i][j][k] = 0.f;

    // prefetch one K-chunk (c in 0..23) into buffer buf
    auto prefetch = [&](int c, int buf) {
        const int seg = c >> 3;
        const __nv_bfloat16* As = (seg == 1) ? Al : Ah;
        const __nv_bfloat16* Bs = (seg == 2) ? Bl : Bh;
        const int k0 = (c & 7) * 64;
        const uint32_t abase = sbase + buf * 32768;
        const uint32_t bbase = abase + 16384;
#pragma unroll
        for (int i = 0; i < 4; i++) {
            const int line = i * 256 + tid;           // 0..1023
            const int row = line >> 3, s16 = line & 7;
            const uint32_t so = SW128((uint32_t)(row * 128 + s16 * 16));
            int ar = row0 + row; if (ar >= M) ar = M - 1;
            cp16(abase + so, As + (size_t)ar * DIM + k0 + s16 * 8);
            cp16(bbase + so, Bs + (size_t)(col0 + row) * DIM + k0 + s16 * 8);
        }
        asm volatile("cp.async.commit_group;" ::: "memory");
    };

    auto compute = [&](int buf) {
        const uint32_t abase = sbase + buf * 32768;
        const uint32_t bbase = abase + 16384;
#pragma unroll
        for (int kk = 0; kk < 4; kk++) {
            uint32_t a[2][4];
#pragma unroll
            for (int mt = 0; mt < 2; mt++) {
                const int r = wm * 32 + mt * 16 + (lane & 15);
                const uint32_t kb = (uint32_t)(kk * 32 + (lane >> 4) * 16);
                ldm4(a[mt], abase + SW128((uint32_t)(r * 128) + kb));
            }
            uint32_t b[8][2];
#pragma unroll
            for (int g = 0; g < 4; g++) {
                const int grp = lane >> 3;
                const int r = wn * 64 + g * 16 + (grp >> 1) * 8 + (lane & 7);
                const uint32_t kb = (uint32_t)(kk * 32 + (grp & 1) * 16);
                uint32_t t[4];
                ldm4(t, bbase + SW128((uint32_t)(r * 128) + kb));
                b[2 * g][0] = t[0]; b[2 * g][1] = t[1];
                b[2 * g + 1][0] = t[2]; b[2 * g + 1][1] = t[3];
            }
#pragma unroll
            for (int mt = 0; mt < 2; mt++)
#pragma unroll
                for (int nt = 0; nt < 8; nt++)
                    mma16816(acc[mt][nt], a[mt], b[nt]);
        }
    };

    prefetch(0, 0);
    for (int c = 0; c < 24; c++) {
        if (c < 23) {
            prefetch(c + 1, (c + 1) & 1);
            asm volatile("cp.async.wait_group 1;" ::: "memory");
        } else {
            asm volatile("cp.async.wait_group 0;" ::: "memory");
        }
        __syncthreads();
        compute(c & 1);
        __syncthreads();
    }

    // ---------------- epilogue (direct from fragments) ----------------
    const int colbase = col0 + wn * 64;
#pragma unroll
    for (int mt = 0; mt < 2; mt++) {
#pragma unroll
        for (int h = 0; h < 2; h++) {
            const int r = row0 + wm * 32 + mt * 16 + h * 8 + (lane >> 2);
            if (MODE == 0) {
                const int src = ei[r];
                const int dst = ei[NE + r];
                const float* xr = x + (size_t)src * DIM;
                float* ap = outf + (size_t)dst * DIM;
#pragma unroll
                for (int nt = 0; nt < 8; nt++) {
                    const int c = colbase + nt * 8 + (lane & 3) * 2;
                    float v0 = acc[mt][nt][h * 2 + 0] + bias[c] + xr[c];
                    float v1 = acc[mt][nt][h * 2 + 1] + bias[c + 1] + xr[c + 1];
                    atomicAdd(ap + c, fmaxf(v0, 0.f));
                    atomicAdd(ap + c + 1, fmaxf(v1, 0.f));
                }
            } else if (r < M) {
                if (MODE == 1) {
#pragma unroll
                    for (int nt = 0; nt < 8; nt++) {
                        const int c = colbase + nt * 8 + (lane & 3) * 2;
                        float v0 = fmaxf(acc[mt][nt][h * 2 + 0] + bias[c], 0.f);
                        float v1 = fmaxf(acc[mt][nt][h * 2 + 1] + bias[c + 1], 0.f);
                        __nv_bfloat16 h0 = __float2bfloat16(v0);
                        __nv_bfloat16 h1 = __float2bfloat16(v1);
                        __nv_bfloat162 hv; hv.x = h0; hv.y = h1;
                        __nv_bfloat162 lv;
                        lv.x = __float2bfloat16(v0 - __bfloat162float(h0));
                        lv.y = __float2bfloat16(v1 - __bfloat162float(h1));
                        *reinterpret_cast<__nv_bfloat162*>(outh + (size_t)r * DIM + c) = hv;
                        *reinterpret_cast<__nv_bfloat162*>(outl + (size_t)r * DIM + c) = lv;
                    }
                } else {
#pragma unroll
                    for (int nt = 0; nt < 8; nt++) {
                        const int c = colbase + nt * 8 + (lane & 3) * 2;
                        float2 v;
                        v.x = acc[mt][nt][h * 2 + 0] + bias[c];
                        v.y = acc[mt][nt][h * 2 + 1] + bias[c + 1];
                        *reinterpret_cast<float2*>(outf + (size_t)r * DIM + c) = v;
                    }
                }
            }
        }
    }
}

// ---------------- BN kernels ----------------
__global__ __launch_bounds__(256) void bn_stats_kernel()
{
    const int t = threadIdx.x;                    // 256 threads -> 2 cols each
    float sx = 0.f, sy = 0.f, qx = 0.f, qy = 0.f;
    const float2* p = reinterpret_cast<const float2*>(g_h2) + t;
    for (int r = blockIdx.x; r < NN; r += gridDim.x) {
        float2 v = p[(size_t)r * 256];
        sx += v.x; sy += v.y;
        qx = fmaf(v.x, v.x, qx); qy = fmaf(v.y, v.y, qy);
    }
    atomicAdd(&g_sum[2 * t], sx);
    atomicAdd(&g_sum[2 * t + 1], sy);
    atomicAdd(&g_sumsq[2 * t], qx);
    atomicAdd(&g_sumsq[2 * t + 1], qy);
}

__global__ void bn_finalize_kernel()
{
    int c = blockIdx.x * blockDim.x + threadIdx.x;
    if (c < DIM) {
        float mean = g_sum[c] * (1.f / NN);
        float var = g_sumsq[c] * (1.f / NN) - mean * mean;
        g_mean[c] = mean;
        g_istd[c] = rsqrtf(var + BN_EPS);
    }
}

__global__ __launch_bounds__(256)
void bn_apply_kernel(const float* __restrict__ gamma,
                     const float* __restrict__ beta,
                     float* __restrict__ out)
{
    int idx = blockIdx.x * blockDim.x + threadIdx.x;
    if (idx >= NN * DIM / 4) return;
    const int c = (idx & (DIM / 4 - 1)) * 4;
    float4 h = reinterpret_cast<const float4*>(g_h2)[idx];
    float4 m = *reinterpret_cast<const float4*>(&g_mean[c]);
    float4 is = *reinterpret_cast<const float4*>(&g_istd[c]);
    float4 ga = *reinterpret_cast<const float4*>(&gamma[c]);
    float4 be = *reinterpret_cast<const float4*>(&beta[c]);
    float4 o;
    o.x = (h.x - m.x) * is.x * ga.x + be.x;
    o.y = (h.y - m.y) * is.y * ga.y + be.y;
    o.z = (h.z - m.z) * is.z * ga.z + be.z;
    o.w = (h.w - m.w) * is.w * ga.w + be.w;
    reinterpret_cast<float4*>(out)[idx] = o;
}

// ---------------- launch ----------------
#define SMEM_GEMM 65536

extern "C" void kernel_launch(void* const* d_in, const int* in_sizes, int n_in,
                              void* d_out, int out_size)
{
    const float* x     = (const float*)d_in[0];
    const int*   ei    = (const int*)d_in[1];
    const float* eattr = (const float*)d_in[2];
    const float* We    = (const float*)d_in[3];
    const float* be    = (const float*)d_in[4];
    const float* W1    = (const float*)d_in[5];
    const float* b1    = (const float*)d_in[6];
    const float* W2    = (const float*)d_in[7];
    const float* b2    = (const float*)d_in[8];
    const float* gamma = (const float*)d_in[9];
    const float* beta  = (const float*)d_in[10];
    float* out = (float*)d_out;

    void *eah, *eal, *aggr, *agh, *agl, *h1h, *h1l, *h2;
    void *weTh, *weTl, *w1Th, *w1Tl, *w2Th, *w2Tl, *sum_p, *sq_p;
    cudaGetSymbolAddress(&eah, g_eah);   cudaGetSymbolAddress(&eal, g_eal);
    cudaGetSymbolAddress(&aggr, g_aggr);
    cudaGetSymbolAddress(&agh, g_agh);   cudaGetSymbolAddress(&agl, g_agl);
    cudaGetSymbolAddress(&h1h, g_h1h);   cudaGetSymbolAddress(&h1l, g_h1l);
    cudaGetSymbolAddress(&h2, g_h2);
    cudaGetSymbolAddress(&weTh, g_weTh); cudaGetSymbolAddress(&weTl, g_weTl);
    cudaGetSymbolAddress(&w1Th, g_w1Th); cudaGetSymbolAddress(&w1Tl, g_w1Tl);
    cudaGetSymbolAddress(&w2Th, g_w2Th); cudaGetSymbolAddress(&w2Tl, g_w2Tl);
    cudaGetSymbolAddress(&sum_p, g_sum); cudaGetSymbolAddress(&sq_p, g_sumsq);

    cudaFuncSetAttribute(mma_gemm_kernel<0>, cudaFuncAttributeMaxDynamicSharedMemorySize, SMEM_GEMM);
    cudaFuncSetAttribute(mma_gemm_kernel<1>, cudaFuncAttributeMaxDynamicSharedMemorySize, SMEM_GEMM);
    cudaFuncSetAttribute(mma_gemm_kernel<2>, cudaFuncAttributeMaxDynamicSharedMemorySize, SMEM_GEMM);

    // aggr = x (GIN eps=0); zero BN accumulators
    cudaMemcpyAsync(aggr, x, sizeof(float) * (size_t)NN * DIM, cudaMemcpyDeviceToDevice);
    cudaMemsetAsync(sum_p, 0, DIM * sizeof(float));
    cudaMemsetAsync(sq_p, 0, DIM * sizeof(float));

    // prep: split eattr; transpose+split weights
    {
        size_t n = (size_t)NE * DIM;
        split_kernel<<<(unsigned)((n + 255) / 256), 256>>>(eattr, (__nv_bfloat16*)eah, (__nv_bfloat16*)eal, n);
        transpose_split_kernel<<<(DIM * DIM + 255) / 256, 256>>>(We, (__nv_bfloat16*)weTh, (__nv_bfloat16*)weTl);
        transpose_split_kernel<<<(DIM * DIM + 255) / 256, 256>>>(W1, (__nv_bfloat16*)w1Th, (__nv_bfloat16*)w1Tl);
        transpose_split_kernel<<<(DIM * DIM + 255) / 256, 256>>>(W2, (__nv_bfloat16*)w2Th, (__nv_bfloat16*)w2Tl);
    }

    // edge GEMM + gather + relu + scatter-add   (NE % 128 == 0)
    mma_gemm_kernel<0><<<dim3(4, NE / 128), 256, SMEM_GEMM>>>(
        (const __nv_bfloat16*)eah, (const __nv_bfloat16*)eal,
        (const __nv_bfloat16*)weTh, (const __nv_bfloat16*)weTl,
        be, NE, x, ei, (float*)aggr, nullptr, nullptr);

    // split aggr to bf16 hi/lo
    {
        size_t n = (size_t)NN * DIM;
        split_kernel<<<(unsigned)((n + 255) / 256), 256>>>((const float*)aggr, (__nv_bfloat16*)agh, (__nv_bfloat16*)agl, n);
    }

    const int nrb = (NN + 127) / 128;
    // h1 = relu(aggr @ W1 + b1) -> bf16 hi/lo
    mma_gemm_kernel<1><<<dim3(4, nrb), 256, SMEM_GEMM>>>(
        (const __nv_bfloat16*)agh, (const __nv_bfloat16*)agl,
        (const __nv_bfloat16*)w1Th, (const __nv_bfloat16*)w1Tl,
        b1, NN, nullptr, nullptr, nullptr, (__nv_bfloat16*)h1h, (__nv_bfloat16*)h1l);

    // h2 = h1 @ W2 + b2
    mma_gemm_kernel<2><<<dim3(4, nrb), 256, SMEM_GEMM>>>(
        (const __nv_bfloat16*)h1h, (const __nv_bfloat16*)h1l,
        (const __nv_bfloat16*)w2Th, (const __nv_bfloat16*)w2Tl,
        b2, NN, nullptr, nullptr, (float*)h2, nullptr, nullptr);

    bn_stats_kernel<<<64, 256>>>();
    bn_finalize_kernel<<<2, 256>>>();

    const int n4 = NN * DIM / 4;
    bn_apply_kernel<<<(n4 + 255) / 256, 256>>>(gamma, beta, out);
}

// round 6
// speedup vs baseline: 3.6226x; 1.0073x over previous
#include <cuda_runtime.h>
#include <cuda_bf16.h>
#include <stdint.h>

#define DIM 512
#define NN 25000
#define NE 400000
#define BN_EPS 1e-5f

// ---------------- scratch (device globals; no runtime alloc) ----------------
__device__ __nv_bfloat16 g_eah[(size_t)NE * DIM];
__device__ __nv_bfloat16 g_eal[(size_t)NE * DIM];
__device__ float g_aggr[(size_t)NN * DIM];
__device__ __nv_bfloat16 g_agh[(size_t)NN * DIM];
__device__ __nv_bfloat16 g_agl[(size_t)NN * DIM];
__device__ __nv_bfloat16 g_h1h[(size_t)NN * DIM];
__device__ __nv_bfloat16 g_h1l[(size_t)NN * DIM];
__device__ float g_h2[(size_t)NN * DIM];
__device__ __nv_bfloat16 g_weTh[DIM * DIM], g_weTl[DIM * DIM];
__device__ __nv_bfloat16 g_w1Th[DIM * DIM], g_w1Tl[DIM * DIM];
__device__ __nv_bfloat16 g_w2Th[DIM * DIM], g_w2Tl[DIM * DIM];
__device__ float g_sum[DIM], g_sumsq[DIM], g_mean[DIM], g_istd[DIM];

// ---------------- helpers ----------------
__device__ __forceinline__ uint32_t smem_u32(const void* p) {
    uint32_t a;
    asm("{ .reg .u64 t; cvta.to.shared.u64 t, %1; cvt.u32.u64 %0, t; }" : "=r"(a) : "l"(p));
    return a;
}
#define SW128(off) ((off) ^ (((off) >> 3) & 0x70))

__device__ __forceinline__ void cp16(uint32_t s, const void* g) {
    asm volatile("cp.async.cg.shared.global [%0], [%1], 16;" :: "r"(s), "l"(g));
}
__device__ __forceinline__ void ldm4(uint32_t* r, uint32_t a) {
    asm volatile("ldmatrix.sync.aligned.m8n8.x4.shared.b16 {%0,%1,%2,%3}, [%4];"
        : "=r"(r[0]), "=r"(r[1]), "=r"(r[2]), "=r"(r[3]) : "r"(a));
}
__device__ __forceinline__ void mma16816(float* d, const uint32_t* a, const uint32_t* b) {
    asm volatile("mma.sync.aligned.m16n8k16.row.col.f32.bf16.bf16.f32 "
        "{%0,%1,%2,%3}, {%4,%5,%6,%7}, {%8,%9}, {%0,%1,%2,%3};"
        : "+f"(d[0]), "+f"(d[1]), "+f"(d[2]), "+f"(d[3])
        : "r"(a[0]), "r"(a[1]), "r"(a[2]), "r"(a[3]), "r"(b[0]), "r"(b[1]));
}

// ---------------- prep kernels ----------------
__global__ __launch_bounds__(256) void split_kernel(const float* __restrict__ src,
                                                    __nv_bfloat16* __restrict__ dh,
                                                    __nv_bfloat16* __restrict__ dl,
                                                    size_t n)
{
    size_t i = (size_t)blockIdx.x * blockDim.x + threadIdx.x;
    if (i < n) {
        float v = src[i];
        __nv_bfloat16 h = __float2bfloat16(v);
        dh[i] = h;
        dl[i] = __float2bfloat16(v - __bfloat162float(h));
    }
}

__global__ __launch_bounds__(256) void transpose_split_kernel(const float* __restrict__ W,
                                                              __nv_bfloat16* __restrict__ dh,
                                                              __nv_bfloat16* __restrict__ dl)
{
    int i = blockIdx.x * blockDim.x + threadIdx.x;   // i = n*512 + k
    if (i < DIM * DIM) {
        int n = i >> 9, k = i & 511;
        float v = W[k * DIM + n];
        __nv_bfloat16 h = __float2bfloat16(v);
        dh[i] = h;
        dl[i] = __float2bfloat16(v - __bfloat162float(h));
    }
}

// ---------------- bf16x3 HMMA GEMM ----------------
// C[M x 512] = A[M x 512] @ B[512 x 512] in split precision:
//   acc = Ah*Bh + Al*Bh + Ah*Bl   (24 K-chunks of 64: seg 0,1,2)
// Tile 128x128, 256 thr, 8 warps (4m x 2n), warp tile 32x64.
// MODE 0: edge: v = relu(acc + bias + x[src]); atomicAdd(aggr[dst], v)
// MODE 1: v = relu(acc + bias) -> bf16 hi/lo
// MODE 2: v = acc + bias -> fp32 store
template <int MODE>
__global__ __launch_bounds__(256, 2)
void mma_gemm_kernel(const __nv_bfloat16* __restrict__ Ah,
                     const __nv_bfloat16* __restrict__ Al,
                     const __nv_bfloat16* __restrict__ Bh,   // transposed [N][K]
                     const __nv_bfloat16* __restrict__ Bl,
                     const float* __restrict__ bias,
                     int M,
                     const float* __restrict__ x,
                     const int* __restrict__ ei,
                     float* __restrict__ outf,
                     __nv_bfloat16* __restrict__ outh,
                     __nv_bfloat16* __restrict__ outl)
{
    extern __shared__ char smem[];                    // 2 x (A 16K + B 16K)
    const uint32_t sbase = smem_u32(smem);
    const int tid = threadIdx.x;
    const int wid = tid >> 5, lane = tid & 31;
    const int wm = wid & 3, wn = wid >> 2;
    const int row0 = blockIdx.y * 128;
    const int col0 = blockIdx.x * 128;

    float acc[2][8][4];
#pragma unroll
    for (int i = 0; i < 2; i++)
#pragma unroll
        for (int j = 0; j < 8; j++)
#pragma unroll
            for (int k = 0; k < 4; k++) acc[i][j][k] = 0.f;

    // prefetch one K-chunk (c in 0..23) into buffer buf
    auto prefetch = [&](int c, int buf) {
        const int seg = c >> 3;
        const __nv_bfloat16* As = (seg == 1) ? Al : Ah;
        const __nv_bfloat16* Bs = (seg == 2) ? Bl : Bh;
        const int k0 = (c & 7) * 64;
        const uint32_t abase = sbase + buf * 32768;
        const uint32_t bbase = abase + 16384;
#pragma unroll
        for (int i = 0; i < 4; i++) {
            const int line = i * 256 + tid;           // 0..1023
            const int row = line >> 3, s16 = line & 7;
            const uint32_t so = SW128((uint32_t)(row * 128 + s16 * 16));
            int ar = row0 + row; if (ar >= M) ar = M - 1;
            cp16(abase + so, As + (size_t)ar * DIM + k0 + s16 * 8);
            cp16(bbase + so, Bs + (size_t)(col0 + row) * DIM + k0 + s16 * 8);
        }
        asm volatile("cp.async.commit_group;" ::: "memory");
    };

    auto compute = [&](int buf) {
        const uint32_t abase = sbase + buf * 32768;
        const uint32_t bbase = abase + 16384;
#pragma unroll
        for (int kk = 0; kk < 4; kk++) {
            uint32_t a[2][4];
#pragma unroll
            for (int mt = 0; mt < 2; mt++) {
                const int r = wm * 32 + mt * 16 + (lane & 15);
                const uint32_t kb = (uint32_t)(kk * 32 + (lane >> 4) * 16);
                ldm4(a[mt], abase + SW128((uint32_t)(r * 128) + kb));
            }
            uint32_t b[8][2];
#pragma unroll
            for (int g = 0; g < 4; g++) {
                const int grp = lane >> 3;
                const int r = wn * 64 + g * 16 + (grp >> 1) * 8 + (lane & 7);
                const uint32_t kb = (uint32_t)(kk * 32 + (grp & 1) * 16);
                uint32_t t[4];
                ldm4(t, bbase + SW128((uint32_t)(r * 128) + kb));
                b[2 * g][0] = t[0]; b[2 * g][1] = t[1];
                b[2 * g + 1][0] = t[2]; b[2 * g + 1][1] = t[3];
            }
#pragma unroll
            for (int mt = 0; mt < 2; mt++)
#pragma unroll
                for (int nt = 0; nt < 8; nt++)
                    mma16816(acc[mt][nt], a[mt], b[nt]);
        }
    };

    prefetch(0, 0);
    for (int c = 0; c < 24; c++) {
        if (c < 23) {
            prefetch(c + 1, (c + 1) & 1);
            asm volatile("cp.async.wait_group 1;" ::: "memory");
        } else {
            asm volatile("cp.async.wait_group 0;" ::: "memory");
        }
        __syncthreads();
        compute(c & 1);
        __syncthreads();
    }

    // ---------------- epilogue (direct from fragments) ----------------
    const int colbase = col0 + wn * 64;
#pragma unroll
    for (int mt = 0; mt < 2; mt++) {
#pragma unroll
        for (int h = 0; h < 2; h++) {
            const int r = row0 + wm * 32 + mt * 16 + h * 8 + (lane >> 2);
            if (MODE == 0) {
                const int src = ei[r];
                const int dst = ei[NE + r];
                const float* xr = x + (size_t)src * DIM;
                float* ap = outf + (size_t)dst * DIM;
#pragma unroll
                for (int nt = 0; nt < 8; nt++) {
                    const int c = colbase + nt * 8 + (lane & 3) * 2;
                    float v0 = acc[mt][nt][h * 2 + 0] + bias[c] + xr[c];
                    float v1 = acc[mt][nt][h * 2 + 1] + bias[c + 1] + xr[c + 1];
                    atomicAdd(ap + c, fmaxf(v0, 0.f));
                    atomicAdd(ap + c + 1, fmaxf(v1, 0.f));
                }
            } else if (r < M) {
                if (MODE == 1) {
#pragma unroll
                    for (int nt = 0; nt < 8; nt++) {
                        const int c = colbase + nt * 8 + (lane & 3) * 2;
                        float v0 = fmaxf(acc[mt][nt][h * 2 + 0] + bias[c], 0.f);
                        float v1 = fmaxf(acc[mt][nt][h * 2 + 1] + bias[c + 1], 0.f);
                        __nv_bfloat16 h0 = __float2bfloat16(v0);
                        __nv_bfloat16 h1 = __float2bfloat16(v1);
                        __nv_bfloat162 hv; hv.x = h0; hv.y = h1;
                        __nv_bfloat162 lv;
                        lv.x = __float2bfloat16(v0 - __bfloat162float(h0));
                        lv.y = __float2bfloat16(v1 - __bfloat162float(h1));
                        *reinterpret_cast<__nv_bfloat162*>(outh + (size_t)r * DIM + c) = hv;
                        *reinterpret_cast<__nv_bfloat162*>(outl + (size_t)r * DIM + c) = lv;
                    }
                } else {
#pragma unroll
                    for (int nt = 0; nt < 8; nt++) {
                        const int c = colbase + nt * 8 + (lane & 3) * 2;
                        float2 v;
                        v.x = acc[mt][nt][h * 2 + 0] + bias[c];
                        v.y = acc[mt][nt][h * 2 + 1] + bias[c + 1];
                        *reinterpret_cast<float2*>(outf + (size_t)r * DIM + c) = v;
                    }
                }
            }
        }
    }
}

// ---------------- BN kernels ----------------
__global__ __launch_bounds__(256) void bn_stats_kernel()
{
    const int t = threadIdx.x;                    // 256 threads -> 2 cols each
    float sx = 0.f, sy = 0.f, qx = 0.f, qy = 0.f;
    const float2* p = reinterpret_cast<const float2*>(g_h2) + t;
    for (int r = blockIdx.x; r < NN; r += gridDim.x) {
        float2 v = p[(size_t)r * 256];
        sx += v.x; sy += v.y;
        qx = fmaf(v.x, v.x, qx); qy = fmaf(v.y, v.y, qy);
    }
    atomicAdd(&g_sum[2 * t], sx);
    atomicAdd(&g_sum[2 * t + 1], sy);
    atomicAdd(&g_sumsq[2 * t], qx);
    atomicAdd(&g_sumsq[2 * t + 1], qy);
}

__global__ void bn_finalize_kernel()
{
    int c = blockIdx.x * blockDim.x + threadIdx.x;
    if (c < DIM) {
        float mean = g_sum[c] * (1.f / NN);
        float var = g_sumsq[c] * (1.f / NN) - mean * mean;
        g_mean[c] = mean;
        g_istd[c] = rsqrtf(var + BN_EPS);
    }
}

__global__ __launch_bounds__(256)
void bn_apply_kernel(const float* __restrict__ gamma,
                     const float* __restrict__ beta,
                     float* __restrict__ out)
{
    int idx = blockIdx.x * blockDim.x + threadIdx.x;
    if (idx >= NN * DIM / 4) return;
    const int c = (idx & (DIM / 4 - 1)) * 4;
    float4 h = reinterpret_cast<const float4*>(g_h2)[idx];
    float4 m = *reinterpret_cast<const float4*>(&g_mean[c]);
    float4 is = *reinterpret_cast<const float4*>(&g_istd[c]);
    float4 ga = *reinterpret_cast<const float4*>(&gamma[c]);
    float4 be = *reinterpret_cast<const float4*>(&beta[c]);
    float4 o;
    o.x = (h.x - m.x) * is.x * ga.x + be.x;
    o.y = (h.y - m.y) * is.y * ga.y + be.y;
    o.z = (h.z - m.z) * is.z * ga.z + be.z;
    o.w = (h.w - m.w) * is.w * ga.w + be.w;
    reinterpret_cast<float4*>(out)[idx] = o;
}

// ---------------- launch ----------------
#define SMEM_GEMM 65536

extern "C" void kernel_launch(void* const* d_in, const int* in_sizes, int n_in,
                              void* d_out, int out_size)
{
    const float* x     = (const float*)d_in[0];
    const int*   ei    = (const int*)d_in[1];
    const float* eattr = (const float*)d_in[2];
    const float* We    = (const float*)d_in[3];
    const float* be    = (const float*)d_in[4];
    const float* W1    = (const float*)d_in[5];
    const float* b1    = (const float*)d_in[6];
    const float* W2    = (const float*)d_in[7];
    const float* b2    = (const float*)d_in[8];
    const float* gamma = (const float*)d_in[9];
    const float* beta  = (const float*)d_in[10];
    float* out = (float*)d_out;

    void *eah, *eal, *aggr, *agh, *agl, *h1h, *h1l, *h2;
    void *weTh, *weTl, *w1Th, *w1Tl, *w2Th, *w2Tl, *sum_p, *sq_p;
    cudaGetSymbolAddress(&eah, g_eah);   cudaGetSymbolAddress(&eal, g_eal);
    cudaGetSymbolAddress(&aggr, g_aggr);
    cudaGetSymbolAddress(&agh, g_agh);   cudaGetSymbolAddress(&agl, g_agl);
    cudaGetSymbolAddress(&h1h, g_h1h);   cudaGetSymbolAddress(&h1l, g_h1l);
    cudaGetSymbolAddress(&h2, g_h2);
    cudaGetSymbolAddress(&weTh, g_weTh); cudaGetSymbolAddress(&weTl, g_weTl);
    cudaGetSymbolAddress(&w1Th, g_w1Th); cudaGetSymbolAddress(&w1Tl, g_w1Tl);
    cudaGetSymbolAddress(&w2Th, g_w2Th); cudaGetSymbolAddress(&w2Tl, g_w2Tl);
    cudaGetSymbolAddress(&sum_p, g_sum); cudaGetSymbolAddress(&sq_p, g_sumsq);

    cudaFuncSetAttribute(mma_gemm_kernel<0>, cudaFuncAttributeMaxDynamicSharedMemorySize, SMEM_GEMM);
    cudaFuncSetAttribute(mma_gemm_kernel<1>, cudaFuncAttributeMaxDynamicSharedMemorySize, SMEM_GEMM);
    cudaFuncSetAttribute(mma_gemm_kernel<2>, cudaFuncAttributeMaxDynamicSharedMemorySize, SMEM_GEMM);

    // aggr = x (GIN eps=0); zero BN accumulators
    cudaMemcpyAsync(aggr, x, sizeof(float) * (size_t)NN * DIM, cudaMemcpyDeviceToDevice);
    cudaMemsetAsync(sum_p, 0, DIM * sizeof(float));
    cudaMemsetAsync(sq_p, 0, DIM * sizeof(float));

    // prep: split eattr; transpose+split weights
    {
        size_t n = (size_t)NE * DIM;
        split_kernel<<<(unsigned)((n + 255) / 256), 256>>>(eattr, (__nv_bfloat16*)eah, (__nv_bfloat16*)eal, n);
        transpose_split_kernel<<<(DIM * DIM + 255) / 256, 256>>>(We, (__nv_bfloat16*)weTh, (__nv_bfloat16*)weTl);
        transpose_split_kernel<<<(DIM * DIM + 255) / 256, 256>>>(W1, (__nv_bfloat16*)w1Th, (__nv_bfloat16*)w1Tl);
        transpose_split_kernel<<<(DIM * DIM + 255) / 256, 256>>>(W2, (__nv_bfloat16*)w2Th, (__nv_bfloat16*)w2Tl);
    }

    // edge GEMM + gather + relu + scatter-add   (NE % 128 == 0)
    mma_gemm_kernel<0><<<dim3(4, NE / 128), 256, SMEM_GEMM>>>(
        (const __nv_bfloat16*)eah, (const __nv_bfloat16*)eal,
        (const __nv_bfloat16*)weTh, (const __nv_bfloat16*)weTl,
        be, NE, x, ei, (float*)aggr, nullptr, nullptr);

    // split aggr to bf16 hi/lo
    {
        size_t n = (size_t)NN * DIM;
        split_kernel<<<(unsigned)((n + 255) / 256), 256>>>((const float*)aggr, (__nv_bfloat16*)agh, (__nv_bfloat16*)agl, n);
    }

    const int nrb = (NN + 127) / 128;
    // h1 = relu(aggr @ W1 + b1) -> bf16 hi/lo
    mma_gemm_kernel<1><<<dim3(4, nrb), 256, SMEM_GEMM>>>(
        (const __nv_bfloat16*)agh, (const __nv_bfloat16*)agl,
        (const __nv_bfloat16*)w1Th, (const __nv_bfloat16*)w1Tl,
        b1, NN, nullptr, nullptr, nullptr, (__nv_bfloat16*)h1h, (__nv_bfloat16*)h1l);

    // h2 = h1 @ W2 + b2
    mma_gemm_kernel<2><<<dim3(4, nrb), 256, SMEM_GEMM>>>(
        (const __nv_bfloat16*)h1h, (const __nv_bfloat16*)h1l,
        (const __nv_bfloat16*)w2Th, (const __nv_bfloat16*)w2Tl,
        b2, NN, nullptr, nullptr, (float*)h2, nullptr, nullptr);

    bn_stats_kernel<<<64, 256>>>();
    bn_finalize_kernel<<<2, 256>>>();

    const int n4 = NN * DIM / 4;
    bn_apply_kernel<<<(n4 + 255) / 256, 256>>>(gamma, beta, out);
}